// round 12
// baseline (speedup 1.0000x reference)
#include <cuda_runtime.h>

// crossCorrelation3D: local 9x9 windowed cross-correlation loss.
// input (32,1,512,512) fp32, target (32,1,512,512) fp32 -> scalar.
//
// Vertical-first separable box sums, 8 columns per thread:
//   - 5 vertical running sums x 8 cols in registers (f32x2 packed).
//   - row y-9 subtracted by reloading from global (L1-resident), guarded.
//   - horizontal 9-sum: halo-only shared exchange (2 LDS.128/channel),
//     middle comes from registers. lo/hi split layout -> conflict-free.
//   - each 128-thread CTA = two independent 64-thread strip-halves
//     (keeps all 4 SMSPs busy despite 64-wide work units).
//   - fused last-CTA finalize (fixed-order -> deterministic).
// Grid = 8 x 32 = 256 CTAs, strips of 32 rows, single wave at occ 2.

#define IMG_W 512
#define IMG_H 512
#define NB    32
#define HT    32
#define NT    128
#define CH_F4   130          // float4 slots per channel: lo[65] + hi[65]
#define REG_F4  (5*CH_F4)    // float4 slots per region (one half, one parity)
#define NPART 256

__device__ float g_part[NPART];
__device__ unsigned g_cnt = 0;

// ---- packed f32x2 helpers ----
struct F2 { unsigned long long v; };

__device__ __forceinline__ F2 f2pk(float lo, float hi) {
    F2 r; asm("mov.b64 %0,{%1,%2};" : "=l"(r.v) : "f"(lo), "f"(hi)); return r;
}
__device__ __forceinline__ void f2up(F2 a, float& lo, float& hi) {
    asm("mov.b64 {%0,%1},%2;" : "=f"(lo), "=f"(hi) : "l"(a.v));
}
__device__ __forceinline__ F2 add2(F2 a, F2 b) {
    F2 r; asm("add.rn.f32x2 %0,%1,%2;" : "=l"(r.v) : "l"(a.v), "l"(b.v)); return r;
}
__device__ __forceinline__ F2 mul2(F2 a, F2 b) {
    F2 r; asm("mul.rn.f32x2 %0,%1,%2;" : "=l"(r.v) : "l"(a.v), "l"(b.v)); return r;
}
__device__ __forceinline__ F2 fma2(F2 a, F2 b, F2 c) {
    F2 r; asm("fma.rn.f32x2 %0,%1,%2,%3;" : "=l"(r.v) : "l"(a.v), "l"(b.v), "l"(c.v)); return r;
}
__device__ __forceinline__ F2 sub2(F2 a, F2 b, F2 neg1) { return fma2(b, neg1, a); }
__device__ __forceinline__ F2 f2z() { F2 r; r.v = 0ull; return r; }

// Load 8 columns of one row pair (I raw, T normalized). Valid iff ymin<=yi<H.
__device__ __forceinline__ void loadrow8(const float* __restrict__ I,
                                         const float* __restrict__ T,
                                         int yi, int ymin, int htid, F2 H,
                                         F2* i, F2* t) {
    if (yi >= ymin && (unsigned)yi < (unsigned)IMG_H) {
        const float4* pI = (const float4*)(I + (size_t)yi * IMG_W);
        const float4* pT = (const float4*)(T + (size_t)yi * IMG_W);
        float4 a = __ldg(pI + 2 * htid), bq = __ldg(pI + 2 * htid + 1);
        float4 c = __ldg(pT + 2 * htid), d = __ldg(pT + 2 * htid + 1);
        i[0] = f2pk(a.x, a.y);  i[1] = f2pk(a.z, a.w);
        i[2] = f2pk(bq.x, bq.y); i[3] = f2pk(bq.z, bq.w);
        t[0] = fma2(f2pk(c.x, c.y), H, H);
        t[1] = fma2(f2pk(c.z, c.w), H, H);
        t[2] = fma2(f2pk(d.x, d.y), H, H);
        t[3] = fma2(f2pk(d.z, d.w), H, H);
    } else {
        #pragma unroll
        for (int k = 0; k < 4; k++) { i[k] = f2z(); t[k] = f2z(); }
    }
}

__device__ __forceinline__ void vupdate(F2 vs[5][4],
                                        const float* __restrict__ Ib,
                                        const float* __restrict__ Tb,
                                        int yn, int ymin, int htid, F2 H, F2 NEG1) {
    F2 nI[4], nT[4], oI[4], oT[4];
    loadrow8(Ib, Tb, yn, -(1 << 30), htid, H, nI, nT);
    loadrow8(Ib, Tb, yn - 9, ymin, htid, H, oI, oT);
    #pragma unroll
    for (int k = 0; k < 4; k++) {
        vs[0][k] = add2(vs[0][k], sub2(nI[k], oI[k], NEG1));
        vs[1][k] = add2(vs[1][k], sub2(nT[k], oT[k], NEG1));
        vs[2][k] = add2(vs[2][k], sub2(mul2(nI[k], nI[k]), mul2(oI[k], oI[k]), NEG1));
        vs[3][k] = add2(vs[3][k], sub2(mul2(nT[k], nT[k]), mul2(oT[k], oT[k]), NEG1));
        vs[4][k] = add2(vs[4][k], sub2(mul2(nI[k], nT[k]), mul2(oI[k], oT[k]), NEG1));
    }
}

// publish: lo slot htid = cols 8t..8t+3 ; hi slot 1+htid = cols 8t+4..8t+7
__device__ __forceinline__ void publish(float4* base5, const F2 vs[5][4], int htid) {
    #pragma unroll
    for (int ch = 0; ch < 5; ch++) {
        float4* base = base5 + ch * CH_F4;
        ulonglong2 u;
        u.x = vs[ch][0].v; u.y = vs[ch][1].v;
        *(ulonglong2*)(base + htid) = u;           // lo[htid]
        u.x = vs[ch][2].v; u.y = vs[ch][3].v;
        *(ulonglong2*)(base + 66 + htid) = u;      // hi[1+htid]
    }
}

__device__ __forceinline__ float cc2(F2 hI, F2 hT, F2 hII, F2 hTT, F2 hIT,
                                     F2 ninv, F2 eps2) {
    F2 cross = fma2(mul2(hI, hT), ninv, hIT);
    F2 tvar  = fma2(mul2(hT, hT), ninv, hTT);
    F2 ivar  = fma2(mul2(hI, hI), ninv, hII);
    F2 den   = fma2(tvar, ivar, eps2);
    F2 num   = mul2(cross, cross);
    float nlo, nhi, dlo, dhi;
    f2up(num, nlo, nhi);
    f2up(den, dlo, dhi);
    return __fdividef(nlo, dlo) + __fdividef(nhi, dhi);
}

__device__ __forceinline__ float consume(const float4* base5, const F2 vs[5][4],
                                         int htid, F2 NINV, F2 EPS2) {
    F2 h[5][4];
    #pragma unroll
    for (int ch = 0; ch < 5; ch++) {
        const float4* base = base5 + ch * CH_F4;
        ulonglong2 L = *(const ulonglong2*)(base + 65 + htid);  // hi[htid]   = left halo
        ulonglong2 R = *(const ulonglong2*)(base + 1 + htid);   // lo[htid+1] = right halo
        float x0, x1, x2, x3, z0, z1, z2, z3;
        F2 tmp;
        tmp.v = L.x; f2up(tmp, x0, x1);
        tmp.v = L.y; f2up(tmp, x2, x3);
        tmp.v = R.x; f2up(tmp, z0, z1);
        tmp.v = R.y; f2up(tmp, z2, z3);
        float y0, y1, y2, y3, y4, y5, y6, y7;
        f2up(vs[ch][0], y0, y1); f2up(vs[ch][1], y2, y3);
        f2up(vs[ch][2], y4, y5); f2up(vs[ch][3], y6, y7);
        float h0 = (((x0 + x1) + (x2 + x3)) + ((y0 + y1) + (y2 + y3))) + y4;
        float h1 = h0 - x0 + y5;
        float h2 = h1 - x1 + y6;
        float h3 = h2 - x2 + y7;
        float h4 = h3 - x3 + z0;
        float h5 = h4 - y0 + z1;
        float h6 = h5 - y1 + z2;
        float h7 = h6 - y2 + z3;
        h[ch][0] = f2pk(h0, h1); h[ch][1] = f2pk(h2, h3);
        h[ch][2] = f2pk(h4, h5); h[ch][3] = f2pk(h6, h7);
    }
    float a = 0.f;
    #pragma unroll
    for (int g = 0; g < 4; g++)
        a += cc2(h[0][g], h[1][g], h[2][g], h[3][g], h[4][g], NINV, EPS2);
    return a;
}

__global__ __launch_bounds__(NT)
void cc_kernel(const float* __restrict__ inp, const float* __restrict__ tgt,
               float* __restrict__ out) {
    extern __shared__ float smf[];          // 4 regions x REG_F4 float4
    float4* sm4 = (float4*)smf;

    const int tid  = threadIdx.x;
    const int half = tid >> 6;
    const int htid = tid & 63;
    const int bx   = blockIdx.x;            // 0..7 (strip pair)
    const int b    = blockIdx.y;            // batch
    const int y0   = (bx * 2 + half) * HT;
    const int ymin = y0 - 4;

    const float* Ib = inp + (size_t)b * IMG_H * IMG_W;
    const float* Tb = tgt + (size_t)b * IMG_H * IMG_W;

    // zero the 2 halo pad slots per channel per region (lo[64], hi[0])
    if (tid < 40) {
        int region = tid / 10, r = tid % 10;
        int ch = r / 2, w = r % 2;
        sm4[region * REG_F4 + ch * CH_F4 + 64 + w] = make_float4(0.f, 0.f, 0.f, 0.f);
    }
    __syncthreads();

    const F2 H    = f2pk(0.5f, 0.5f);
    const F2 NEG1 = f2pk(-1.f, -1.f);
    const F2 NINV = f2pk(-1.f / 81.f, -1.f / 81.f);
    const F2 EPS2 = f2pk(1e-5f, 1e-5f);

    F2 vs[5][4];
    #pragma unroll
    for (int c = 0; c < 5; c++)
        #pragma unroll
        for (int k = 0; k < 4; k++) vs[c][k] = f2z();
    float acc = 0.f;

    // halo rows y0-4 .. y0+3 (accumulate only)
    #pragma unroll
    for (int it = 0; it < 8; ++it)
        vupdate(vs, Ib, Tb, y0 - 4 + it, ymin, htid, H, NEG1);

    float4* reg0 = sm4 + (0 * 2 + half) * REG_F4;
    float4* reg1 = sm4 + (1 * 2 + half) * REG_F4;

    for (int it = 8; it < HT + 8; ++it) {
        vupdate(vs, Ib, Tb, y0 - 4 + it, ymin, htid, H, NEG1);
        float4* buf = (it & 1) ? reg1 : reg0;
        publish(buf, vs, htid);
        __syncthreads();
        acc += consume(buf, vs, htid, NINV, EPS2);
    }

    // block reduction over all 128 threads (both halves)
    __syncthreads();
    smf[tid] = acc;
    __syncthreads();
    #pragma unroll
    for (int s = NT / 2; s > 0; s >>= 1) {
        if (tid < s) smf[tid] += smf[tid + s];
        __syncthreads();
    }

    // fused finalize: last CTA reduces all 256 partials in fixed order
    __shared__ unsigned s_last;
    if (tid == 0) {
        g_part[b * 8 + bx] = smf[0];
        __threadfence();
        unsigned r = atomicAdd(&g_cnt, 1u);
        s_last = (r == NPART - 1) ? 1u : 0u;
    }
    __syncthreads();
    if (s_last) {
        __threadfence();
        float t = g_part[tid] + g_part[tid + NT];
        __syncthreads();
        smf[tid] = t;
        __syncthreads();
        #pragma unroll
        for (int s = NT / 2; s > 0; s >>= 1) {
            if (tid < s) smf[tid] += smf[tid + s];
            __syncthreads();
        }
        if (tid == 0) {
            out[0] = -smf[0] * (1.0f / 8388608.0f);
            g_cnt = 0;   // reset for next graph replay
        }
    }
}

extern "C" void kernel_launch(void* const* d_in, const int* in_sizes, int n_in,
                              void* d_out, int out_size) {
    const float* inp = (const float*)d_in[0];
    const float* tgt = (const float*)d_in[1];
    size_t smem = (size_t)(4 * REG_F4) * sizeof(float4);   // 41600 B
    cudaFuncSetAttribute(cc_kernel, cudaFuncAttributeMaxDynamicSharedMemorySize, (int)smem);
    dim3 grid(8, NB);   // 256 CTAs, two 32-row strips per CTA
    cc_kernel<<<grid, NT, smem>>>(inp, tgt, (float*)d_out);
}

// round 13
// speedup vs baseline: 1.3406x; 1.3406x over previous
#include <cuda_runtime.h>

// crossCorrelation3D: local 9x9 windowed cross-correlation loss.
// input (32,1,512,512) fp32, target (32,1,512,512) fp32 -> scalar.
//
// Vertical-first separable box sums (proven R8 config) + fused finalize:
//   - 5 vertical running sums (I,T,II,TT,IT) in registers (f32x2 packed).
//   - row y-9 subtracted by reloading from global (L1-resident), guarded.
//   - horizontal 9-sum: halo from a small double-buffered shared exchange,
//     middle 8 values straight from registers; one __syncthreads per row.
//   - packed f32x2 (FFMA2) arithmetic for all element-wise math.
//   - final reduction fused via last-CTA pattern (fixed order -> deterministic).
// Grid = 18 ytiles x 32 batches = 576 CTAs, 128 thr x 4 cols, occ 4.

#define IMG_W 512
#define IMG_H 512
#define NB    32
#define HT    29
#define YT    18            // 17*29=493, last tile 19 rows
#define NT    128
#define CSTRIDE 520         // 4 pad + 512 + 4 pad
#define BUFF  (5*CSTRIDE)   // one exchange buffer (5 channels)
#define NPART (YT*NB)       // 576

__device__ float g_part[NPART];
__device__ unsigned g_cnt = 0;

// ---- packed f32x2 helpers ----
struct F2 { unsigned long long v; };

__device__ __forceinline__ F2 f2pk(float lo, float hi) {
    F2 r; asm("mov.b64 %0,{%1,%2};" : "=l"(r.v) : "f"(lo), "f"(hi)); return r;
}
__device__ __forceinline__ void f2up(F2 a, float& lo, float& hi) {
    asm("mov.b64 {%0,%1},%2;" : "=f"(lo), "=f"(hi) : "l"(a.v));
}
__device__ __forceinline__ F2 add2(F2 a, F2 b) {
    F2 r; asm("add.rn.f32x2 %0,%1,%2;" : "=l"(r.v) : "l"(a.v), "l"(b.v)); return r;
}
__device__ __forceinline__ F2 mul2(F2 a, F2 b) {
    F2 r; asm("mul.rn.f32x2 %0,%1,%2;" : "=l"(r.v) : "l"(a.v), "l"(b.v)); return r;
}
__device__ __forceinline__ F2 fma2(F2 a, F2 b, F2 c) {
    F2 r; asm("fma.rn.f32x2 %0,%1,%2,%3;" : "=l"(r.v) : "l"(a.v), "l"(b.v), "l"(c.v)); return r;
}
__device__ __forceinline__ F2 sub2(F2 a, F2 b, F2 neg1) { return fma2(b, neg1, a); }
__device__ __forceinline__ F2 f2z() { F2 r; r.v = 0ull; return r; }

// Load one row pair (I raw, T normalized). Valid iff ymin <= yi < IMG_H.
__device__ __forceinline__ void loadrow(const float* __restrict__ I,
                                        const float* __restrict__ T,
                                        int yi, int ymin, int tid, F2 H,
                                        F2& i0, F2& i1, F2& t0, F2& t1) {
    if (yi >= ymin && (unsigned)yi < (unsigned)IMG_H) {
        float4 a = __ldg((const float4*)(I + (size_t)yi * IMG_W) + tid);
        float4 b = __ldg((const float4*)(T + (size_t)yi * IMG_W) + tid);
        i0 = f2pk(a.x, a.y); i1 = f2pk(a.z, a.w);
        t0 = fma2(f2pk(b.x, b.y), H, H);   // (t+1)*0.5
        t1 = fma2(f2pk(b.z, b.w), H, H);
    } else {
        i0 = f2z(); i1 = f2z(); t0 = f2z(); t1 = f2z();
    }
}

// horizontal 9-sum over 12-col window (L halo | middle from regs | R halo)
__device__ __forceinline__ void hsum9p(F2 L0, F2 L1, F2 O0, F2 O1, F2 R0, F2 R1,
                                       F2& hA, F2& hB) {
    F2 Q = add2(add2(L0, L1), add2(O0, O1));
    float qlo, qhi, w0, w1, w2, wx, w8, w9, w10, w11;
    f2up(Q, qlo, qhi);
    f2up(L0, w0, w1);
    f2up(L1, w2, wx);
    f2up(R0, w8, w9);
    f2up(R1, w10, w11);
    float h0 = qlo + qhi + w8;
    float h1 = h0 - w0 + w9;
    float h2 = h1 - w1 + w10;
    float h3 = h2 - w2 + w11;
    hA = f2pk(h0, h1);
    hB = f2pk(h2, h3);
}

// packed cc for 2 outputs
__device__ __forceinline__ float cc2(F2 hI, F2 hT, F2 hII, F2 hTT, F2 hIT,
                                     F2 ninv, F2 eps2) {
    F2 cross = fma2(mul2(hI, hT), ninv, hIT);
    F2 tvar  = fma2(mul2(hT, hT), ninv, hTT);
    F2 ivar  = fma2(mul2(hI, hI), ninv, hII);
    F2 den   = fma2(tvar, ivar, eps2);
    F2 num   = mul2(cross, cross);
    float nlo, nhi, dlo, dhi;
    f2up(num, nlo, nhi);
    f2up(den, dlo, dhi);
    return __fdividef(nlo, dlo) + __fdividef(nhi, dhi);
}

__global__ __launch_bounds__(NT, 4)
void cc_kernel(const float* __restrict__ inp, const float* __restrict__ tgt,
               float* __restrict__ out) {
    extern __shared__ float sm[];   // 2 * BUFF floats (double-buffered exchange)

    const int tid = threadIdx.x;
    const int bx  = blockIdx.x;     // ytile
    const int b   = blockIdx.y;     // batch
    const int y0  = bx * HT;
    const int ymin = y0 - 4;        // first accumulated row index
    const int rows_out = min(HT, IMG_H - y0);
    const int iters = rows_out + 8;

    const float* Ib = inp + (size_t)b * IMG_H * IMG_W;
    const float* Tb = tgt + (size_t)b * IMG_H * IMG_W;

    // zero the left/right pads of both buffers (5 channels each)
    for (int i = tid; i < 2 * 5 * 8; i += NT) {
        int bf = i / 40, r = i % 40;
        int ch = r / 8, s = r % 8;
        int idx = (s < 4) ? s : (512 + s);  // 0..3 or 516..519
        sm[bf * BUFF + ch * CSTRIDE + idx] = 0.f;
    }
    __syncthreads();

    const F2 H    = f2pk(0.5f, 0.5f);
    const F2 NEG1 = f2pk(-1.f, -1.f);
    const F2 NINV = f2pk(-1.f / 81.f, -1.f / 81.f);
    const F2 EPS2 = f2pk(1e-5f, 1e-5f);

    F2 vI0 = f2z(), vI1 = f2z(), vT0 = f2z(), vT1 = f2z();
    F2 vII0 = f2z(), vII1 = f2z(), vTT0 = f2z(), vTT1 = f2z();
    F2 vIT0 = f2z(), vIT1 = f2z();
    float acc = 0.f;

    for (int it = 0; it < iters; ++it) {
        const int yn = y0 - 4 + it;     // new row entering the window
        const int yo = yn - 9;          // old row leaving

        F2 nI0, nI1, nT0, nT1, oI0, oI1, oT0, oT1;
        loadrow(Ib, Tb, yn, -(1 << 30), tid, H, nI0, nI1, nT0, nT1);
        // old row: subtract only rows that were actually accumulated
        loadrow(Ib, Tb, yo, ymin, tid, H, oI0, oI1, oT0, oT1);

        vI0 = add2(vI0, sub2(nI0, oI0, NEG1));
        vI1 = add2(vI1, sub2(nI1, oI1, NEG1));
        vT0 = add2(vT0, sub2(nT0, oT0, NEG1));
        vT1 = add2(vT1, sub2(nT1, oT1, NEG1));
        vII0 = add2(vII0, sub2(mul2(nI0, nI0), mul2(oI0, oI0), NEG1));
        vII1 = add2(vII1, sub2(mul2(nI1, nI1), mul2(oI1, oI1), NEG1));
        vTT0 = add2(vTT0, sub2(mul2(nT0, nT0), mul2(oT0, oT0), NEG1));
        vTT1 = add2(vTT1, sub2(mul2(nT1, nT1), mul2(oT1, oT1), NEG1));
        vIT0 = add2(vIT0, sub2(mul2(nI0, nT0), mul2(oI0, oT0), NEG1));
        vIT1 = add2(vIT1, sub2(mul2(nI1, nT1), mul2(oI1, oT1), NEG1));

        if (it >= 8) {
            float* buf = sm + (it & 1) * BUFF;
            {
                ulonglong2 u;
                u.x = vI0.v;  u.y = vI1.v;
                *(ulonglong2*)&buf[0 * CSTRIDE + 4 + 4 * tid] = u;
                u.x = vT0.v;  u.y = vT1.v;
                *(ulonglong2*)&buf[1 * CSTRIDE + 4 + 4 * tid] = u;
                u.x = vII0.v; u.y = vII1.v;
                *(ulonglong2*)&buf[2 * CSTRIDE + 4 + 4 * tid] = u;
                u.x = vTT0.v; u.y = vTT1.v;
                *(ulonglong2*)&buf[3 * CSTRIDE + 4 + 4 * tid] = u;
                u.x = vIT0.v; u.y = vIT1.v;
                *(ulonglong2*)&buf[4 * CSTRIDE + 4 + 4 * tid] = u;
            }
            __syncthreads();

            F2 hIA, hIB, hTA, hTB, hIIA, hIIB, hTTA, hTTB, hITA, hITB;
            {
                ulonglong2 L, R; F2 l0, l1, r0, r1;
                L = *(ulonglong2*)&buf[0 * CSTRIDE + 4 * tid];
                R = *(ulonglong2*)&buf[0 * CSTRIDE + 8 + 4 * tid];
                l0.v = L.x; l1.v = L.y; r0.v = R.x; r1.v = R.y;
                hsum9p(l0, l1, vI0, vI1, r0, r1, hIA, hIB);
                L = *(ulonglong2*)&buf[1 * CSTRIDE + 4 * tid];
                R = *(ulonglong2*)&buf[1 * CSTRIDE + 8 + 4 * tid];
                l0.v = L.x; l1.v = L.y; r0.v = R.x; r1.v = R.y;
                hsum9p(l0, l1, vT0, vT1, r0, r1, hTA, hTB);
                L = *(ulonglong2*)&buf[2 * CSTRIDE + 4 * tid];
                R = *(ulonglong2*)&buf[2 * CSTRIDE + 8 + 4 * tid];
                l0.v = L.x; l1.v = L.y; r0.v = R.x; r1.v = R.y;
                hsum9p(l0, l1, vII0, vII1, r0, r1, hIIA, hIIB);
                L = *(ulonglong2*)&buf[3 * CSTRIDE + 4 * tid];
                R = *(ulonglong2*)&buf[3 * CSTRIDE + 8 + 4 * tid];
                l0.v = L.x; l1.v = L.y; r0.v = R.x; r1.v = R.y;
                hsum9p(l0, l1, vTT0, vTT1, r0, r1, hTTA, hTTB);
                L = *(ulonglong2*)&buf[4 * CSTRIDE + 4 * tid];
                R = *(ulonglong2*)&buf[4 * CSTRIDE + 8 + 4 * tid];
                l0.v = L.x; l1.v = L.y; r0.v = R.x; r1.v = R.y;
                hsum9p(l0, l1, vIT0, vIT1, r0, r1, hITA, hITB);
            }

            acc += cc2(hIA, hTA, hIIA, hTTA, hITA, NINV, EPS2);
            acc += cc2(hIB, hTB, hIIB, hTTB, hITB, NINV, EPS2);
        }
    }

    // deterministic block reduction (reuse exchange buffer)
    __syncthreads();
    sm[tid] = acc;
    __syncthreads();
    #pragma unroll
    for (int s = NT / 2; s > 0; s >>= 1) {
        if (tid < s) sm[tid] += sm[tid + s];
        __syncthreads();
    }

    // fused finalize: last CTA reduces all 576 partials in fixed order
    __shared__ unsigned s_last;
    if (tid == 0) {
        g_part[b * YT + bx] = sm[0];
        __threadfence();
        unsigned r = atomicAdd(&g_cnt, 1u);
        s_last = (r == NPART - 1) ? 1u : 0u;
    }
    __syncthreads();
    if (s_last) {
        __threadfence();
        float t = 0.f;
        #pragma unroll
        for (int k = 0; k < 5; k++) {            // fixed order -> deterministic
            int idx = tid + k * NT;
            if (idx < NPART) t += g_part[idx];
        }
        sm[tid] = t;
        __syncthreads();
        #pragma unroll
        for (int s = NT / 2; s > 0; s >>= 1) {
            if (tid < s) sm[tid] += sm[tid + s];
            __syncthreads();
        }
        if (tid == 0) {
            out[0] = -sm[0] * (1.0f / 8388608.0f);
            g_cnt = 0;   // reset for next graph replay
        }
    }
}

extern "C" void kernel_launch(void* const* d_in, const int* in_sizes, int n_in,
                              void* d_out, int out_size) {
    const float* inp = (const float*)d_in[0];
    const float* tgt = (const float*)d_in[1];
    size_t smem = (size_t)(2 * BUFF) * sizeof(float);   // 20.8 KB
    cudaFuncSetAttribute(cc_kernel, cudaFuncAttributeMaxDynamicSharedMemorySize, (int)smem);
    dim3 grid(YT, NB);   // (18, 32) = 576 CTAs
    cc_kernel<<<grid, NT, smem>>>(inp, tgt, (float*)d_out);
}

// round 14
// speedup vs baseline: 1.3635x; 1.0171x over previous
#include <cuda_runtime.h>

// crossCorrelation3D: local 9x9 windowed cross-correlation loss.
// input (32,1,512,512) fp32, target (32,1,512,512) fp32 -> scalar.
//
// Vertical-first separable box sums + fused finalize, occupancy-6 config:
//   - 5 vertical running sums (I,T,II,TT,IT) in registers (f32x2 packed).
//   - row y-9 subtracted by reloading from global (L1/L2-resident).
//   - halo loop split: first 9 iterations skip the (dead) old-row loads.
//   - horizontal 9-sum: halo from double-buffered shared exchange, middle
//     from registers; one __syncthreads per output row.
//   - packed f32x2 (FFMA2) arithmetic; fused last-CTA finalize.
// Grid = 26 ytiles x 32 batches = 832 CTAs, 128 thr x 4 cols, occ 6 (1 wave).

#define IMG_W 512
#define IMG_H 512
#define NB    32
#define HT    20
#define YT    26            // 25*20=500, last tile 12 rows
#define NT    128
#define CSTRIDE 520         // 4 pad + 512 + 4 pad
#define BUFF  (5*CSTRIDE)   // one exchange buffer (5 channels)
#define NPART (YT*NB)       // 832

__device__ float g_part[NPART];
__device__ unsigned g_cnt = 0;

// ---- packed f32x2 helpers ----
struct F2 { unsigned long long v; };

__device__ __forceinline__ F2 f2pk(float lo, float hi) {
    F2 r; asm("mov.b64 %0,{%1,%2};" : "=l"(r.v) : "f"(lo), "f"(hi)); return r;
}
__device__ __forceinline__ void f2up(F2 a, float& lo, float& hi) {
    asm("mov.b64 {%0,%1},%2;" : "=f"(lo), "=f"(hi) : "l"(a.v));
}
__device__ __forceinline__ F2 add2(F2 a, F2 b) {
    F2 r; asm("add.rn.f32x2 %0,%1,%2;" : "=l"(r.v) : "l"(a.v), "l"(b.v)); return r;
}
__device__ __forceinline__ F2 mul2(F2 a, F2 b) {
    F2 r; asm("mul.rn.f32x2 %0,%1,%2;" : "=l"(r.v) : "l"(a.v), "l"(b.v)); return r;
}
__device__ __forceinline__ F2 fma2(F2 a, F2 b, F2 c) {
    F2 r; asm("fma.rn.f32x2 %0,%1,%2,%3;" : "=l"(r.v) : "l"(a.v), "l"(b.v), "l"(c.v)); return r;
}
__device__ __forceinline__ F2 sub2(F2 a, F2 b, F2 neg1) { return fma2(b, neg1, a); }
__device__ __forceinline__ F2 f2z() { F2 r; r.v = 0ull; return r; }

struct VS { F2 v[5][2]; };

// Load one row pair (I raw, T normalized). Valid iff 0 <= yi < IMG_H.
__device__ __forceinline__ void loadrow(const float* __restrict__ I,
                                        const float* __restrict__ T,
                                        int yi, int tid, F2 H,
                                        F2& i0, F2& i1, F2& t0, F2& t1) {
    if ((unsigned)yi < (unsigned)IMG_H) {
        float4 a = __ldg((const float4*)(I + (size_t)yi * IMG_W) + tid);
        float4 b = __ldg((const float4*)(T + (size_t)yi * IMG_W) + tid);
        i0 = f2pk(a.x, a.y); i1 = f2pk(a.z, a.w);
        t0 = fma2(f2pk(b.x, b.y), H, H);   // (t+1)*0.5
        t1 = fma2(f2pk(b.z, b.w), H, H);
    } else {
        i0 = f2z(); i1 = f2z(); t0 = f2z(); t1 = f2z();
    }
}

// add new row yn into the running sums
__device__ __forceinline__ void vadd(VS& s, const float* __restrict__ Ib,
                                     const float* __restrict__ Tb,
                                     int yn, int tid, F2 H) {
    F2 nI0, nI1, nT0, nT1;
    loadrow(Ib, Tb, yn, tid, H, nI0, nI1, nT0, nT1);
    s.v[0][0] = add2(s.v[0][0], nI0);
    s.v[0][1] = add2(s.v[0][1], nI1);
    s.v[1][0] = add2(s.v[1][0], nT0);
    s.v[1][1] = add2(s.v[1][1], nT1);
    s.v[2][0] = fma2(nI0, nI0, s.v[2][0]);
    s.v[2][1] = fma2(nI1, nI1, s.v[2][1]);
    s.v[3][0] = fma2(nT0, nT0, s.v[3][0]);
    s.v[3][1] = fma2(nT1, nT1, s.v[3][1]);
    s.v[4][0] = fma2(nI0, nT0, s.v[4][0]);
    s.v[4][1] = fma2(nI1, nT1, s.v[4][1]);
}

// add new row yn, subtract old row yn-9 (old guaranteed accumulated)
__device__ __forceinline__ void vaddsub(VS& s, const float* __restrict__ Ib,
                                        const float* __restrict__ Tb,
                                        int yn, int tid, F2 H, F2 NEG1) {
    F2 nI0, nI1, nT0, nT1, oI0, oI1, oT0, oT1;
    loadrow(Ib, Tb, yn, tid, H, nI0, nI1, nT0, nT1);
    loadrow(Ib, Tb, yn - 9, tid, H, oI0, oI1, oT0, oT1);
    s.v[0][0] = add2(s.v[0][0], sub2(nI0, oI0, NEG1));
    s.v[0][1] = add2(s.v[0][1], sub2(nI1, oI1, NEG1));
    s.v[1][0] = add2(s.v[1][0], sub2(nT0, oT0, NEG1));
    s.v[1][1] = add2(s.v[1][1], sub2(nT1, oT1, NEG1));
    s.v[2][0] = add2(s.v[2][0], sub2(mul2(nI0, nI0), mul2(oI0, oI0), NEG1));
    s.v[2][1] = add2(s.v[2][1], sub2(mul2(nI1, nI1), mul2(oI1, oI1), NEG1));
    s.v[3][0] = add2(s.v[3][0], sub2(mul2(nT0, nT0), mul2(oT0, oT0), NEG1));
    s.v[3][1] = add2(s.v[3][1], sub2(mul2(nT1, nT1), mul2(oT1, oT1), NEG1));
    s.v[4][0] = add2(s.v[4][0], sub2(mul2(nI0, nT0), mul2(oI0, oT0), NEG1));
    s.v[4][1] = add2(s.v[4][1], sub2(mul2(nI1, nT1), mul2(oI1, oT1), NEG1));
}

// horizontal 9-sum over 12-col window (L halo | middle from regs | R halo)
__device__ __forceinline__ void hsum9p(F2 L0, F2 L1, F2 O0, F2 O1, F2 R0, F2 R1,
                                       F2& hA, F2& hB) {
    F2 Q = add2(add2(L0, L1), add2(O0, O1));
    float qlo, qhi, w0, w1, w2, wx, w8, w9, w10, w11;
    f2up(Q, qlo, qhi);
    f2up(L0, w0, w1);
    f2up(L1, w2, wx);
    f2up(R0, w8, w9);
    f2up(R1, w10, w11);
    float h0 = qlo + qhi + w8;
    float h1 = h0 - w0 + w9;
    float h2 = h1 - w1 + w10;
    float h3 = h2 - w2 + w11;
    hA = f2pk(h0, h1);
    hB = f2pk(h2, h3);
}

__device__ __forceinline__ float cc2(F2 hI, F2 hT, F2 hII, F2 hTT, F2 hIT,
                                     F2 ninv, F2 eps2) {
    F2 cross = fma2(mul2(hI, hT), ninv, hIT);
    F2 tvar  = fma2(mul2(hT, hT), ninv, hTT);
    F2 ivar  = fma2(mul2(hI, hI), ninv, hII);
    F2 den   = fma2(tvar, ivar, eps2);
    F2 num   = mul2(cross, cross);
    float nlo, nhi, dlo, dhi;
    f2up(num, nlo, nhi);
    f2up(den, dlo, dhi);
    return __fdividef(nlo, dlo) + __fdividef(nhi, dhi);
}

// publish vertical sums, sync, horizontal sums + cc for one output row
__device__ __forceinline__ float emit(float* buf, const VS& s, int tid,
                                      F2 NINV, F2 EPS2) {
    {
        ulonglong2 u;
        #pragma unroll
        for (int ch = 0; ch < 5; ch++) {
            u.x = s.v[ch][0].v; u.y = s.v[ch][1].v;
            *(ulonglong2*)&buf[ch * CSTRIDE + 4 + 4 * tid] = u;
        }
    }
    __syncthreads();

    F2 h[5][2];
    #pragma unroll
    for (int ch = 0; ch < 5; ch++) {
        ulonglong2 L = *(ulonglong2*)&buf[ch * CSTRIDE + 4 * tid];
        ulonglong2 R = *(ulonglong2*)&buf[ch * CSTRIDE + 8 + 4 * tid];
        F2 l0, l1, r0, r1;
        l0.v = L.x; l1.v = L.y; r0.v = R.x; r1.v = R.y;
        hsum9p(l0, l1, s.v[ch][0], s.v[ch][1], r0, r1, h[ch][0], h[ch][1]);
    }
    return cc2(h[0][0], h[1][0], h[2][0], h[3][0], h[4][0], NINV, EPS2)
         + cc2(h[0][1], h[1][1], h[2][1], h[3][1], h[4][1], NINV, EPS2);
}

__global__ __launch_bounds__(NT, 6)
void cc_kernel(const float* __restrict__ inp, const float* __restrict__ tgt,
               float* __restrict__ out) {
    extern __shared__ float sm[];   // 2 * BUFF floats (double-buffered exchange)

    const int tid = threadIdx.x;
    const int bx  = blockIdx.x;     // ytile
    const int b   = blockIdx.y;     // batch
    const int y0  = bx * HT;
    const int rows_out = min(HT, IMG_H - y0);
    const int iters = rows_out + 8;

    const float* Ib = inp + (size_t)b * IMG_H * IMG_W;
    const float* Tb = tgt + (size_t)b * IMG_H * IMG_W;

    // zero the left/right pads of both buffers (5 channels each)
    for (int i = tid; i < 2 * 5 * 8; i += NT) {
        int bf = i / 40, r = i % 40;
        int ch = r / 8, s = r % 8;
        int idx = (s < 4) ? s : (512 + s);  // 0..3 or 516..519
        sm[bf * BUFF + ch * CSTRIDE + idx] = 0.f;
    }
    __syncthreads();

    const F2 H    = f2pk(0.5f, 0.5f);
    const F2 NEG1 = f2pk(-1.f, -1.f);
    const F2 NINV = f2pk(-1.f / 81.f, -1.f / 81.f);
    const F2 EPS2 = f2pk(1e-5f, 1e-5f);

    VS s;
    #pragma unroll
    for (int c = 0; c < 5; c++) { s.v[c][0] = f2z(); s.v[c][1] = f2z(); }
    float acc = 0.f;

    // halo iterations 0..7: accumulate only (no old row exists yet)
    #pragma unroll
    for (int it = 0; it < 8; ++it)
        vadd(s, Ib, Tb, y0 - 4 + it, tid, H);

    // it = 8: add only (old row y0-5 was never accumulated), first output
    vadd(s, Ib, Tb, y0 + 4, tid, H);
    acc += emit(sm, s, tid, NINV, EPS2);

    // it = 9..: steady state, old row always accumulated (bounds check only)
    for (int it = 9; it < iters; ++it) {
        vaddsub(s, Ib, Tb, y0 - 4 + it, tid, H, NEG1);
        acc += emit(sm + (it & 1) * BUFF, s, tid, NINV, EPS2);
    }

    // deterministic block reduction (reuse exchange buffer)
    __syncthreads();
    sm[tid] = acc;
    __syncthreads();
    #pragma unroll
    for (int st = NT / 2; st > 0; st >>= 1) {
        if (tid < st) sm[tid] += sm[tid + st];
        __syncthreads();
    }

    // fused finalize: last CTA reduces all partials in fixed order
    __shared__ unsigned s_last;
    if (tid == 0) {
        g_part[b * YT + bx] = sm[0];
        __threadfence();
        unsigned r = atomicAdd(&g_cnt, 1u);
        s_last = (r == NPART - 1) ? 1u : 0u;
    }
    __syncthreads();
    if (s_last) {
        __threadfence();
        float t = 0.f;
        #pragma unroll
        for (int k = 0; k < (NPART + NT - 1) / NT; k++) {   // fixed order
            int idx = tid + k * NT;
            if (idx < NPART) t += g_part[idx];
        }
        sm[tid] = t;
        __syncthreads();
        #pragma unroll
        for (int st = NT / 2; st > 0; st >>= 1) {
            if (tid < st) sm[tid] += sm[tid + st];
            __syncthreads();
        }
        if (tid == 0) {
            out[0] = -sm[0] * (1.0f / 8388608.0f);
            g_cnt = 0;   // reset for next graph replay
        }
    }
}

extern "C" void kernel_launch(void* const* d_in, const int* in_sizes, int n_in,
                              void* d_out, int out_size) {
    const float* inp = (const float*)d_in[0];
    const float* tgt = (const float*)d_in[1];
    size_t smem = (size_t)(2 * BUFF) * sizeof(float);   // 20.8 KB
    cudaFuncSetAttribute(cc_kernel, cudaFuncAttributeMaxDynamicSharedMemorySize, (int)smem);
    dim3 grid(YT, NB);   // (26, 32) = 832 CTAs, one wave at occ 6
    cc_kernel<<<grid, NT, smem>>>(inp, tgt, (float*)d_out);
}

// round 15
// speedup vs baseline: 1.4102x; 1.0343x over previous
#include <cuda_runtime.h>

// crossCorrelation3D: local 9x9 windowed cross-correlation loss.
// input (32,1,512,512) fp32, target (32,1,512,512) fp32 -> scalar.
//
// Vertical-first separable box sums + fused finalize, pipelined loads:
//   - 5 vertical running sums (I,T,II,TT,IT) in registers (f32x2 packed).
//   - NEW row prefetched one iteration ahead (DRAM latency hidden);
//     old row (y-9) reloaded same-iteration (L1-resident at occ 5).
//   - halo loop split: first 9 iterations skip the (dead) old-row loads.
//   - horizontal 9-sum: halo via double-buffered shared exchange, middle
//     from registers; one __syncthreads per output row.
//   - packed f32x2 (FFMA2) arithmetic; fused last-CTA finalize.
// Grid = 22 ytiles x 32 batches = 704 CTAs, 128 thr x 4 cols, occ 5 (1 wave).

#define IMG_W 512
#define IMG_H 512
#define NB    32
#define HT    24
#define YT    22            // 21*24=504, last tile 8 rows
#define NT    128
#define CSTRIDE 520         // 4 pad + 512 + 4 pad
#define BUFF  (5*CSTRIDE)   // one exchange buffer (5 channels)
#define NPART (YT*NB)       // 704

__device__ float g_part[NPART];
__device__ unsigned g_cnt = 0;

// ---- packed f32x2 helpers ----
struct F2 { unsigned long long v; };

__device__ __forceinline__ F2 f2pk(float lo, float hi) {
    F2 r; asm("mov.b64 %0,{%1,%2};" : "=l"(r.v) : "f"(lo), "f"(hi)); return r;
}
__device__ __forceinline__ void f2up(F2 a, float& lo, float& hi) {
    asm("mov.b64 {%0,%1},%2;" : "=f"(lo), "=f"(hi) : "l"(a.v));
}
__device__ __forceinline__ F2 add2(F2 a, F2 b) {
    F2 r; asm("add.rn.f32x2 %0,%1,%2;" : "=l"(r.v) : "l"(a.v), "l"(b.v)); return r;
}
__device__ __forceinline__ F2 mul2(F2 a, F2 b) {
    F2 r; asm("mul.rn.f32x2 %0,%1,%2;" : "=l"(r.v) : "l"(a.v), "l"(b.v)); return r;
}
__device__ __forceinline__ F2 fma2(F2 a, F2 b, F2 c) {
    F2 r; asm("fma.rn.f32x2 %0,%1,%2,%3;" : "=l"(r.v) : "l"(a.v), "l"(b.v), "l"(c.v)); return r;
}
__device__ __forceinline__ F2 sub2(F2 a, F2 b, F2 neg1) { return fma2(b, neg1, a); }
__device__ __forceinline__ F2 f2z() { F2 r; r.v = 0ull; return r; }

struct ROW { F2 i0, i1, t0, t1; };
struct VS  { F2 v[5][2]; };

// Load one row pair (I raw, T normalized). Valid iff 0 <= yi < IMG_H.
__device__ __forceinline__ ROW loadrow(const float* __restrict__ I,
                                       const float* __restrict__ T,
                                       int yi, int tid, F2 H) {
    ROW r;
    if ((unsigned)yi < (unsigned)IMG_H) {
        float4 a = __ldg((const float4*)(I + (size_t)yi * IMG_W) + tid);
        float4 b = __ldg((const float4*)(T + (size_t)yi * IMG_W) + tid);
        r.i0 = f2pk(a.x, a.y); r.i1 = f2pk(a.z, a.w);
        r.t0 = fma2(f2pk(b.x, b.y), H, H);   // (t+1)*0.5
        r.t1 = fma2(f2pk(b.z, b.w), H, H);
    } else {
        r.i0 = f2z(); r.i1 = f2z(); r.t0 = f2z(); r.t1 = f2z();
    }
    return r;
}

// add row n into the running sums
__device__ __forceinline__ void vadd(VS& s, const ROW& n) {
    s.v[0][0] = add2(s.v[0][0], n.i0);
    s.v[0][1] = add2(s.v[0][1], n.i1);
    s.v[1][0] = add2(s.v[1][0], n.t0);
    s.v[1][1] = add2(s.v[1][1], n.t1);
    s.v[2][0] = fma2(n.i0, n.i0, s.v[2][0]);
    s.v[2][1] = fma2(n.i1, n.i1, s.v[2][1]);
    s.v[3][0] = fma2(n.t0, n.t0, s.v[3][0]);
    s.v[3][1] = fma2(n.t1, n.t1, s.v[3][1]);
    s.v[4][0] = fma2(n.i0, n.t0, s.v[4][0]);
    s.v[4][1] = fma2(n.i1, n.t1, s.v[4][1]);
}

// add row n, subtract row o
__device__ __forceinline__ void vaddsub(VS& s, const ROW& n, const ROW& o, F2 NEG1) {
    s.v[0][0] = add2(s.v[0][0], sub2(n.i0, o.i0, NEG1));
    s.v[0][1] = add2(s.v[0][1], sub2(n.i1, o.i1, NEG1));
    s.v[1][0] = add2(s.v[1][0], sub2(n.t0, o.t0, NEG1));
    s.v[1][1] = add2(s.v[1][1], sub2(n.t1, o.t1, NEG1));
    s.v[2][0] = add2(s.v[2][0], sub2(mul2(n.i0, n.i0), mul2(o.i0, o.i0), NEG1));
    s.v[2][1] = add2(s.v[2][1], sub2(mul2(n.i1, n.i1), mul2(o.i1, o.i1), NEG1));
    s.v[3][0] = add2(s.v[3][0], sub2(mul2(n.t0, n.t0), mul2(o.t0, o.t0), NEG1));
    s.v[3][1] = add2(s.v[3][1], sub2(mul2(n.t1, n.t1), mul2(o.t1, o.t1), NEG1));
    s.v[4][0] = add2(s.v[4][0], sub2(mul2(n.i0, n.t0), mul2(o.i0, o.t0), NEG1));
    s.v[4][1] = add2(s.v[4][1], sub2(mul2(n.i1, n.t1), mul2(o.i1, o.t1), NEG1));
}

// horizontal 9-sum over 12-col window (L halo | middle from regs | R halo)
__device__ __forceinline__ void hsum9p(F2 L0, F2 L1, F2 O0, F2 O1, F2 R0, F2 R1,
                                       F2& hA, F2& hB) {
    F2 Q = add2(add2(L0, L1), add2(O0, O1));
    float qlo, qhi, w0, w1, w2, wx, w8, w9, w10, w11;
    f2up(Q, qlo, qhi);
    f2up(L0, w0, w1);
    f2up(L1, w2, wx);
    f2up(R0, w8, w9);
    f2up(R1, w10, w11);
    float h0 = qlo + qhi + w8;
    float h1 = h0 - w0 + w9;
    float h2 = h1 - w1 + w10;
    float h3 = h2 - w2 + w11;
    hA = f2pk(h0, h1);
    hB = f2pk(h2, h3);
}

__device__ __forceinline__ float cc2(F2 hI, F2 hT, F2 hII, F2 hTT, F2 hIT,
                                     F2 ninv, F2 eps2) {
    F2 cross = fma2(mul2(hI, hT), ninv, hIT);
    F2 tvar  = fma2(mul2(hT, hT), ninv, hTT);
    F2 ivar  = fma2(mul2(hI, hI), ninv, hII);
    F2 den   = fma2(tvar, ivar, eps2);
    F2 num   = mul2(cross, cross);
    float nlo, nhi, dlo, dhi;
    f2up(num, nlo, nhi);
    f2up(den, dlo, dhi);
    return __fdividef(nlo, dlo) + __fdividef(nhi, dhi);
}

// publish vertical sums, sync, horizontal sums + cc for one output row
__device__ __forceinline__ float emit(float* buf, const VS& s, int tid,
                                      F2 NINV, F2 EPS2) {
    {
        ulonglong2 u;
        #pragma unroll
        for (int ch = 0; ch < 5; ch++) {
            u.x = s.v[ch][0].v; u.y = s.v[ch][1].v;
            *(ulonglong2*)&buf[ch * CSTRIDE + 4 + 4 * tid] = u;
        }
    }
    __syncthreads();

    F2 h[5][2];
    #pragma unroll
    for (int ch = 0; ch < 5; ch++) {
        ulonglong2 L = *(ulonglong2*)&buf[ch * CSTRIDE + 4 * tid];
        ulonglong2 R = *(ulonglong2*)&buf[ch * CSTRIDE + 8 + 4 * tid];
        F2 l0, l1, r0, r1;
        l0.v = L.x; l1.v = L.y; r0.v = R.x; r1.v = R.y;
        hsum9p(l0, l1, s.v[ch][0], s.v[ch][1], r0, r1, h[ch][0], h[ch][1]);
    }
    return cc2(h[0][0], h[1][0], h[2][0], h[3][0], h[4][0], NINV, EPS2)
         + cc2(h[0][1], h[1][1], h[2][1], h[3][1], h[4][1], NINV, EPS2);
}

__global__ __launch_bounds__(NT, 5)
void cc_kernel(const float* __restrict__ inp, const float* __restrict__ tgt,
               float* __restrict__ out) {
    extern __shared__ float sm[];   // 2 * BUFF floats (double-buffered exchange)

    const int tid = threadIdx.x;
    const int bx  = blockIdx.x;     // ytile
    const int b   = blockIdx.y;     // batch
    const int y0  = bx * HT;
    const int rows_out = min(HT, IMG_H - y0);
    const int iters = rows_out + 8;

    const float* Ib = inp + (size_t)b * IMG_H * IMG_W;
    const float* Tb = tgt + (size_t)b * IMG_H * IMG_W;

    // zero the left/right pads of both buffers (5 channels each)
    for (int i = tid; i < 2 * 5 * 8; i += NT) {
        int bf = i / 40, r = i % 40;
        int ch = r / 8, s = r % 8;
        int idx = (s < 4) ? s : (512 + s);  // 0..3 or 516..519
        sm[bf * BUFF + ch * CSTRIDE + idx] = 0.f;
    }
    __syncthreads();

    const F2 H    = f2pk(0.5f, 0.5f);
    const F2 NEG1 = f2pk(-1.f, -1.f);
    const F2 NINV = f2pk(-1.f / 81.f, -1.f / 81.f);
    const F2 EPS2 = f2pk(1e-5f, 1e-5f);

    VS s;
    #pragma unroll
    for (int c = 0; c < 5; c++) { s.v[c][0] = f2z(); s.v[c][1] = f2z(); }
    float acc = 0.f;

    // prime the pipeline: load row y0-4
    ROW cur = loadrow(Ib, Tb, y0 - 4, tid, H);

    // halo iterations 0..7: prefetch next, accumulate current (no old row)
    #pragma unroll
    for (int it = 0; it < 8; ++it) {
        ROW nxt = loadrow(Ib, Tb, y0 - 3 + it, tid, H);
        vadd(s, cur);
        cur = nxt;
    }

    // it = 8: old row y0-5 was never accumulated -> add-only, first output
    {
        ROW nxt = loadrow(Ib, Tb, y0 + 5, tid, H);
        vadd(s, cur);
        acc += emit(sm, s, tid, NINV, EPS2);     // parity (8&1)=0
        cur = nxt;
    }

    // steady state: old row always accumulated; prefetch next new row
    for (int it = 9; it < iters; ++it) {
        const int yn = y0 - 4 + it;
        ROW old = loadrow(Ib, Tb, yn - 9, tid, H);
        ROW nxt = loadrow(Ib, Tb, (it + 1 < iters) ? yn + 1 : -1, tid, H);
        vaddsub(s, cur, old, NEG1);
        acc += emit(sm + (it & 1) * BUFF, s, tid, NINV, EPS2);
        cur = nxt;
    }

    // deterministic block reduction (reuse exchange buffer)
    __syncthreads();
    sm[tid] = acc;
    __syncthreads();
    #pragma unroll
    for (int st = NT / 2; st > 0; st >>= 1) {
        if (tid < st) sm[tid] += sm[tid + st];
        __syncthreads();
    }

    // fused finalize: last CTA reduces all partials in fixed order
    __shared__ unsigned s_last;
    if (tid == 0) {
        g_part[b * YT + bx] = sm[0];
        __threadfence();
        unsigned r = atomicAdd(&g_cnt, 1u);
        s_last = (r == NPART - 1) ? 1u : 0u;
    }
    __syncthreads();
    if (s_last) {
        __threadfence();
        float t = 0.f;
        #pragma unroll
        for (int k = 0; k < (NPART + NT - 1) / NT; k++) {   // fixed order
            int idx = tid + k * NT;
            if (idx < NPART) t += g_part[idx];
        }
        sm[tid] = t;
        __syncthreads();
        #pragma unroll
        for (int st = NT / 2; st > 0; st >>= 1) {
            if (tid < st) sm[tid] += sm[tid + st];
            __syncthreads();
        }
        if (tid == 0) {
            out[0] = -sm[0] * (1.0f / 8388608.0f);
            g_cnt = 0;   // reset for next graph replay
        }
    }
}

extern "C" void kernel_launch(void* const* d_in, const int* in_sizes, int n_in,
                              void* d_out, int out_size) {
    const float* inp = (const float*)d_in[0];
    const float* tgt = (const float*)d_in[1];
    size_t smem = (size_t)(2 * BUFF) * sizeof(float);   // 20.8 KB
    cudaFuncSetAttribute(cc_kernel, cudaFuncAttributeMaxDynamicSharedMemorySize, (int)smem);
    dim3 grid(YT, NB);   // (22, 32) = 704 CTAs, one wave at occ 5
    cc_kernel<<<grid, NT, smem>>>(inp, tgt, (float*)d_out);
}

// round 16
// speedup vs baseline: 1.4586x; 1.0344x over previous
#include <cuda_runtime.h>

// crossCorrelation3D: local 9x9 windowed cross-correlation loss.
// input (32,1,512,512) fp32, target (32,1,512,512) fp32 -> scalar.
//
// Vertical-first separable box sums + fused finalize, fully pipelined loads:
//   - 5 vertical running sums (I,T,II,TT,IT) in registers (f32x2 packed).
//   - BOTH next-iteration rows (new yn+1, old yn-8) are prefetched BEFORE
//     emit of the current row, giving them ~120 instructions of cover:
//     DRAM (new) and L2 (old) latency both hidden.
//   - halo loop split: first 9 iterations skip the (dead) old-row loads.
//   - horizontal 9-sum: halo via double-buffered shared exchange, middle
//     from registers; one __syncthreads per output row.
//   - packed f32x2 (FFMA2) arithmetic; fused last-CTA finalize.
// Grid = 22 ytiles x 32 batches = 704 CTAs, 128 thr x 4 cols, occ 5 (1 wave).

#define IMG_W 512
#define IMG_H 512
#define NB    32
#define HT    24
#define YT    22            // 21*24=504, last tile 8 rows
#define NT    128
#define CSTRIDE 520         // 4 pad + 512 + 4 pad
#define BUFF  (5*CSTRIDE)   // one exchange buffer (5 channels)
#define NPART (YT*NB)       // 704

__device__ float g_part[NPART];
__device__ unsigned g_cnt = 0;

// ---- packed f32x2 helpers ----
struct F2 { unsigned long long v; };

__device__ __forceinline__ F2 f2pk(float lo, float hi) {
    F2 r; asm("mov.b64 %0,{%1,%2};" : "=l"(r.v) : "f"(lo), "f"(hi)); return r;
}
__device__ __forceinline__ void f2up(F2 a, float& lo, float& hi) {
    asm("mov.b64 {%0,%1},%2;" : "=f"(lo), "=f"(hi) : "l"(a.v));
}
__device__ __forceinline__ F2 add2(F2 a, F2 b) {
    F2 r; asm("add.rn.f32x2 %0,%1,%2;" : "=l"(r.v) : "l"(a.v), "l"(b.v)); return r;
}
__device__ __forceinline__ F2 mul2(F2 a, F2 b) {
    F2 r; asm("mul.rn.f32x2 %0,%1,%2;" : "=l"(r.v) : "l"(a.v), "l"(b.v)); return r;
}
__device__ __forceinline__ F2 fma2(F2 a, F2 b, F2 c) {
    F2 r; asm("fma.rn.f32x2 %0,%1,%2,%3;" : "=l"(r.v) : "l"(a.v), "l"(b.v), "l"(c.v)); return r;
}
__device__ __forceinline__ F2 sub2(F2 a, F2 b, F2 neg1) { return fma2(b, neg1, a); }
__device__ __forceinline__ F2 f2z() { F2 r; r.v = 0ull; return r; }

struct ROW { F2 i0, i1, t0, t1; };
struct VS  { F2 v[5][2]; };

// Load one row pair (I raw, T normalized). Valid iff 0 <= yi < IMG_H.
__device__ __forceinline__ ROW loadrow(const float* __restrict__ I,
                                       const float* __restrict__ T,
                                       int yi, int tid, F2 H) {
    ROW r;
    if ((unsigned)yi < (unsigned)IMG_H) {
        float4 a = __ldg((const float4*)(I + (size_t)yi * IMG_W) + tid);
        float4 b = __ldg((const float4*)(T + (size_t)yi * IMG_W) + tid);
        r.i0 = f2pk(a.x, a.y); r.i1 = f2pk(a.z, a.w);
        r.t0 = fma2(f2pk(b.x, b.y), H, H);   // (t+1)*0.5
        r.t1 = fma2(f2pk(b.z, b.w), H, H);
    } else {
        r.i0 = f2z(); r.i1 = f2z(); r.t0 = f2z(); r.t1 = f2z();
    }
    return r;
}

// add row n into the running sums
__device__ __forceinline__ void vadd(VS& s, const ROW& n) {
    s.v[0][0] = add2(s.v[0][0], n.i0);
    s.v[0][1] = add2(s.v[0][1], n.i1);
    s.v[1][0] = add2(s.v[1][0], n.t0);
    s.v[1][1] = add2(s.v[1][1], n.t1);
    s.v[2][0] = fma2(n.i0, n.i0, s.v[2][0]);
    s.v[2][1] = fma2(n.i1, n.i1, s.v[2][1]);
    s.v[3][0] = fma2(n.t0, n.t0, s.v[3][0]);
    s.v[3][1] = fma2(n.t1, n.t1, s.v[3][1]);
    s.v[4][0] = fma2(n.i0, n.t0, s.v[4][0]);
    s.v[4][1] = fma2(n.i1, n.t1, s.v[4][1]);
}

// add row n, subtract row o
__device__ __forceinline__ void vaddsub(VS& s, const ROW& n, const ROW& o, F2 NEG1) {
    s.v[0][0] = add2(s.v[0][0], sub2(n.i0, o.i0, NEG1));
    s.v[0][1] = add2(s.v[0][1], sub2(n.i1, o.i1, NEG1));
    s.v[1][0] = add2(s.v[1][0], sub2(n.t0, o.t0, NEG1));
    s.v[1][1] = add2(s.v[1][1], sub2(n.t1, o.t1, NEG1));
    s.v[2][0] = add2(s.v[2][0], sub2(mul2(n.i0, n.i0), mul2(o.i0, o.i0), NEG1));
    s.v[2][1] = add2(s.v[2][1], sub2(mul2(n.i1, n.i1), mul2(o.i1, o.i1), NEG1));
    s.v[3][0] = add2(s.v[3][0], sub2(mul2(n.t0, n.t0), mul2(o.t0, o.t0), NEG1));
    s.v[3][1] = add2(s.v[3][1], sub2(mul2(n.t1, n.t1), mul2(o.t1, o.t1), NEG1));
    s.v[4][0] = add2(s.v[4][0], sub2(mul2(n.i0, n.t0), mul2(o.i0, o.t0), NEG1));
    s.v[4][1] = add2(s.v[4][1], sub2(mul2(n.i1, n.t1), mul2(o.i1, o.t1), NEG1));
}

// horizontal 9-sum over 12-col window (L halo | middle from regs | R halo)
__device__ __forceinline__ void hsum9p(F2 L0, F2 L1, F2 O0, F2 O1, F2 R0, F2 R1,
                                       F2& hA, F2& hB) {
    F2 Q = add2(add2(L0, L1), add2(O0, O1));
    float qlo, qhi, w0, w1, w2, wx, w8, w9, w10, w11;
    f2up(Q, qlo, qhi);
    f2up(L0, w0, w1);
    f2up(L1, w2, wx);
    f2up(R0, w8, w9);
    f2up(R1, w10, w11);
    float h0 = qlo + qhi + w8;
    float h1 = h0 - w0 + w9;
    float h2 = h1 - w1 + w10;
    float h3 = h2 - w2 + w11;
    hA = f2pk(h0, h1);
    hB = f2pk(h2, h3);
}

__device__ __forceinline__ float cc2(F2 hI, F2 hT, F2 hII, F2 hTT, F2 hIT,
                                     F2 ninv, F2 eps2) {
    F2 cross = fma2(mul2(hI, hT), ninv, hIT);
    F2 tvar  = fma2(mul2(hT, hT), ninv, hTT);
    F2 ivar  = fma2(mul2(hI, hI), ninv, hII);
    F2 den   = fma2(tvar, ivar, eps2);
    F2 num   = mul2(cross, cross);
    float nlo, nhi, dlo, dhi;
    f2up(num, nlo, nhi);
    f2up(den, dlo, dhi);
    return __fdividef(nlo, dlo) + __fdividef(nhi, dhi);
}

// publish vertical sums, sync, horizontal sums + cc for one output row
__device__ __forceinline__ float emit(float* buf, const VS& s, int tid,
                                      F2 NINV, F2 EPS2) {
    {
        ulonglong2 u;
        #pragma unroll
        for (int ch = 0; ch < 5; ch++) {
            u.x = s.v[ch][0].v; u.y = s.v[ch][1].v;
            *(ulonglong2*)&buf[ch * CSTRIDE + 4 + 4 * tid] = u;
        }
    }
    __syncthreads();

    F2 h[5][2];
    #pragma unroll
    for (int ch = 0; ch < 5; ch++) {
        ulonglong2 L = *(ulonglong2*)&buf[ch * CSTRIDE + 4 * tid];
        ulonglong2 R = *(ulonglong2*)&buf[ch * CSTRIDE + 8 + 4 * tid];
        F2 l0, l1, r0, r1;
        l0.v = L.x; l1.v = L.y; r0.v = R.x; r1.v = R.y;
        hsum9p(l0, l1, s.v[ch][0], s.v[ch][1], r0, r1, h[ch][0], h[ch][1]);
    }
    return cc2(h[0][0], h[1][0], h[2][0], h[3][0], h[4][0], NINV, EPS2)
         + cc2(h[0][1], h[1][1], h[2][1], h[3][1], h[4][1], NINV, EPS2);
}

__global__ __launch_bounds__(NT, 5)
void cc_kernel(const float* __restrict__ inp, const float* __restrict__ tgt,
               float* __restrict__ out) {
    extern __shared__ float sm[];   // 2 * BUFF floats (double-buffered exchange)

    const int tid = threadIdx.x;
    const int bx  = blockIdx.x;     // ytile
    const int b   = blockIdx.y;     // batch
    const int y0  = bx * HT;
    const int rows_out = min(HT, IMG_H - y0);
    const int iters = rows_out + 8;

    const float* Ib = inp + (size_t)b * IMG_H * IMG_W;
    const float* Tb = tgt + (size_t)b * IMG_H * IMG_W;

    // zero the left/right pads of both buffers (5 channels each)
    for (int i = tid; i < 2 * 5 * 8; i += NT) {
        int bf = i / 40, r = i % 40;
        int ch = r / 8, s = r % 8;
        int idx = (s < 4) ? s : (512 + s);  // 0..3 or 516..519
        sm[bf * BUFF + ch * CSTRIDE + idx] = 0.f;
    }
    __syncthreads();

    const F2 H    = f2pk(0.5f, 0.5f);
    const F2 NEG1 = f2pk(-1.f, -1.f);
    const F2 NINV = f2pk(-1.f / 81.f, -1.f / 81.f);
    const F2 EPS2 = f2pk(1e-5f, 1e-5f);

    VS s;
    #pragma unroll
    for (int c = 0; c < 5; c++) { s.v[c][0] = f2z(); s.v[c][1] = f2z(); }
    float acc = 0.f;

    // prime the pipeline: load row y0-4
    ROW cur = loadrow(Ib, Tb, y0 - 4, tid, H);

    // halo iterations 0..7: prefetch next, accumulate current (no old row)
    #pragma unroll
    for (int it = 0; it < 8; ++it) {
        ROW nxt = loadrow(Ib, Tb, y0 - 3 + it, tid, H);
        vadd(s, cur);
        cur = nxt;
    }

    // it = 8: old row (y0-13+8 = y0-5) was never accumulated -> add-only.
    // Prefetch BOTH rows for it=9 (new y0+5, old y0-4) before emit.
    ROW oldp;
    {
        vadd(s, cur);                               // cur = row y0+4, dies here
        oldp = loadrow(Ib, Tb, y0 - 4, tid, H);     // old for it=9
        cur  = loadrow(Ib, Tb, y0 + 5, tid, H);     // new for it=9
        acc += emit(sm, s, tid, NINV, EPS2);        // parity (8&1)=0
    }

    // steady state: consume prefetched pair, prefetch next pair, then emit.
    // Both loads get the whole emit body (~120 instr) to land.
    for (int it = 9; it < iters; ++it) {
        vaddsub(s, cur, oldp, NEG1);                // cur/oldp die here
        const int more = (it + 1 < iters);
        oldp = loadrow(Ib, Tb, more ? (y0 - 12 + it) : -1, tid, H);  // (yn+1)-9
        cur  = loadrow(Ib, Tb, more ? (y0 - 3 + it)  : -1, tid, H);  // yn+1
        acc += emit(sm + (it & 1) * BUFF, s, tid, NINV, EPS2);
    }

    // deterministic block reduction (reuse exchange buffer)
    __syncthreads();
    sm[tid] = acc;
    __syncthreads();
    #pragma unroll
    for (int st = NT / 2; st > 0; st >>= 1) {
        if (tid < st) sm[tid] += sm[tid + st];
        __syncthreads();
    }

    // fused finalize: last CTA reduces all partials in fixed order
    __shared__ unsigned s_last;
    if (tid == 0) {
        g_part[b * YT + bx] = sm[0];
        __threadfence();
        unsigned r = atomicAdd(&g_cnt, 1u);
        s_last = (r == NPART - 1) ? 1u : 0u;
    }
    __syncthreads();
    if (s_last) {
        __threadfence();
        float t = 0.f;
        #pragma unroll
        for (int k = 0; k < (NPART + NT - 1) / NT; k++) {   // fixed order
            int idx = tid + k * NT;
            if (idx < NPART) t += g_part[idx];
        }
        sm[tid] = t;
        __syncthreads();
        #pragma unroll
        for (int st = NT / 2; st > 0; st >>= 1) {
            if (tid < st) sm[tid] += sm[tid + st];
            __syncthreads();
        }
        if (tid == 0) {
            out[0] = -sm[0] * (1.0f / 8388608.0f);
            g_cnt = 0;   // reset for next graph replay
        }
    }
}

extern "C" void kernel_launch(void* const* d_in, const int* in_sizes, int n_in,
                              void* d_out, int out_size) {
    const float* inp = (const float*)d_in[0];
    const float* tgt = (const float*)d_in[1];
    size_t smem = (size_t)(2 * BUFF) * sizeof(float);   // 20.8 KB
    cudaFuncSetAttribute(cc_kernel, cudaFuncAttributeMaxDynamicSharedMemorySize, (int)smem);
    dim3 grid(YT, NB);   // (22, 32) = 704 CTAs, one wave at occ 5
    cc_kernel<<<grid, NT, smem>>>(inp, tgt, (float*)d_out);
}

// round 17
// speedup vs baseline: 1.4907x; 1.0220x over previous
#include <cuda_runtime.h>

// crossCorrelation3D: local 9x9 windowed cross-correlation loss.
// input (32,1,512,512) fp32, target (32,1,512,512) fp32 -> scalar.
//
// Vertical-first separable box sums + fused finalize, pipelined loads:
//   - 5 vertical running sums in registers (f32x2 packed).
//   - both next-iteration rows prefetched before emit (latency hidden).
//   - INTERIOR tiles (bx 1..YT-2): check-free pointer-increment loads.
//   - horizontal 9-sum: halo via double-buffered shared exchange, middle
//     from registers; one __syncthreads per output row.
//   - epilogue: 4 divisions folded into ONE __fdividef per row (rational
//     pairwise combine, packed).
// Grid = 22 ytiles x 32 batches = 704 CTAs, 128 thr x 4 cols, occ 5 (1 wave).

#define IMG_W 512
#define IMG_H 512
#define NB    32
#define HT    24
#define YT    22            // 21*24=504, last tile 8 rows
#define NT    128
#define CSTRIDE 520         // 4 pad + 512 + 4 pad
#define BUFF  (5*CSTRIDE)   // one exchange buffer (5 channels)
#define NPART (YT*NB)       // 704

__device__ float g_part[NPART];
__device__ unsigned g_cnt = 0;

// ---- packed f32x2 helpers ----
struct F2 { unsigned long long v; };

__device__ __forceinline__ F2 f2pk(float lo, float hi) {
    F2 r; asm("mov.b64 %0,{%1,%2};" : "=l"(r.v) : "f"(lo), "f"(hi)); return r;
}
__device__ __forceinline__ void f2up(F2 a, float& lo, float& hi) {
    asm("mov.b64 {%0,%1},%2;" : "=f"(lo), "=f"(hi) : "l"(a.v));
}
__device__ __forceinline__ F2 add2(F2 a, F2 b) {
    F2 r; asm("add.rn.f32x2 %0,%1,%2;" : "=l"(r.v) : "l"(a.v), "l"(b.v)); return r;
}
__device__ __forceinline__ F2 mul2(F2 a, F2 b) {
    F2 r; asm("mul.rn.f32x2 %0,%1,%2;" : "=l"(r.v) : "l"(a.v), "l"(b.v)); return r;
}
__device__ __forceinline__ F2 fma2(F2 a, F2 b, F2 c) {
    F2 r; asm("fma.rn.f32x2 %0,%1,%2,%3;" : "=l"(r.v) : "l"(a.v), "l"(b.v), "l"(c.v)); return r;
}
__device__ __forceinline__ F2 sub2(F2 a, F2 b, F2 neg1) { return fma2(b, neg1, a); }
__device__ __forceinline__ F2 f2z() { F2 r; r.v = 0ull; return r; }

struct ROW { F2 i0, i1, t0, t1; };
struct VS  { F2 v[5][2]; };

// pointer-based row load (no checks): pI/pT already point at this thread's
// float4 within the row.
__device__ __forceinline__ ROW ldrowP(const float* __restrict__ pI,
                                      const float* __restrict__ pT, F2 H) {
    ROW r;
    float4 a = __ldg((const float4*)pI);
    float4 b = __ldg((const float4*)pT);
    r.i0 = f2pk(a.x, a.y); r.i1 = f2pk(a.z, a.w);
    r.t0 = fma2(f2pk(b.x, b.y), H, H);   // (t+1)*0.5
    r.t1 = fma2(f2pk(b.z, b.w), H, H);
    return r;
}

// index-based row load with bounds check (edge tiles)
__device__ __forceinline__ ROW loadrow(const float* __restrict__ I,
                                       const float* __restrict__ T,
                                       int yi, int tid, F2 H) {
    ROW r;
    if ((unsigned)yi < (unsigned)IMG_H) {
        r = ldrowP(I + (size_t)yi * IMG_W + 4 * tid,
                   T + (size_t)yi * IMG_W + 4 * tid, H);
    } else {
        r.i0 = f2z(); r.i1 = f2z(); r.t0 = f2z(); r.t1 = f2z();
    }
    return r;
}

__device__ __forceinline__ void vadd(VS& s, const ROW& n) {
    s.v[0][0] = add2(s.v[0][0], n.i0);
    s.v[0][1] = add2(s.v[0][1], n.i1);
    s.v[1][0] = add2(s.v[1][0], n.t0);
    s.v[1][1] = add2(s.v[1][1], n.t1);
    s.v[2][0] = fma2(n.i0, n.i0, s.v[2][0]);
    s.v[2][1] = fma2(n.i1, n.i1, s.v[2][1]);
    s.v[3][0] = fma2(n.t0, n.t0, s.v[3][0]);
    s.v[3][1] = fma2(n.t1, n.t1, s.v[3][1]);
    s.v[4][0] = fma2(n.i0, n.t0, s.v[4][0]);
    s.v[4][1] = fma2(n.i1, n.t1, s.v[4][1]);
}

__device__ __forceinline__ void vaddsub(VS& s, const ROW& n, const ROW& o, F2 NEG1) {
    s.v[0][0] = add2(s.v[0][0], sub2(n.i0, o.i0, NEG1));
    s.v[0][1] = add2(s.v[0][1], sub2(n.i1, o.i1, NEG1));
    s.v[1][0] = add2(s.v[1][0], sub2(n.t0, o.t0, NEG1));
    s.v[1][1] = add2(s.v[1][1], sub2(n.t1, o.t1, NEG1));
    s.v[2][0] = add2(s.v[2][0], sub2(mul2(n.i0, n.i0), mul2(o.i0, o.i0), NEG1));
    s.v[2][1] = add2(s.v[2][1], sub2(mul2(n.i1, n.i1), mul2(o.i1, o.i1), NEG1));
    s.v[3][0] = add2(s.v[3][0], sub2(mul2(n.t0, n.t0), mul2(o.t0, o.t0), NEG1));
    s.v[3][1] = add2(s.v[3][1], sub2(mul2(n.t1, n.t1), mul2(o.t1, o.t1), NEG1));
    s.v[4][0] = add2(s.v[4][0], sub2(mul2(n.i0, n.t0), mul2(o.i0, o.t0), NEG1));
    s.v[4][1] = add2(s.v[4][1], sub2(mul2(n.i1, n.t1), mul2(o.i1, o.t1), NEG1));
}

// horizontal 9-sum over 12-col window (L halo | middle from regs | R halo)
__device__ __forceinline__ void hsum9p(F2 L0, F2 L1, F2 O0, F2 O1, F2 R0, F2 R1,
                                       F2& hA, F2& hB) {
    F2 Q = add2(add2(L0, L1), add2(O0, O1));
    float qlo, qhi, w0, w1, w2, wx, w8, w9, w10, w11;
    f2up(Q, qlo, qhi);
    f2up(L0, w0, w1);
    f2up(L1, w2, wx);
    f2up(R0, w8, w9);
    f2up(R1, w10, w11);
    float h0 = qlo + qhi + w8;
    float h1 = h0 - w0 + w9;
    float h2 = h1 - w1 + w10;
    float h3 = h2 - w2 + w11;
    hA = f2pk(h0, h1);
    hB = f2pk(h2, h3);
}

// cc core for one packed pair: returns num and den (no division)
__device__ __forceinline__ void ccnd(F2 hI, F2 hT, F2 hII, F2 hTT, F2 hIT,
                                     F2 ninv, F2 eps2, F2& num, F2& den) {
    F2 cross = fma2(mul2(hI, hT), ninv, hIT);
    F2 tvar  = fma2(mul2(hT, hT), ninv, hTT);
    F2 ivar  = fma2(mul2(hI, hI), ninv, hII);
    den = fma2(tvar, ivar, eps2);
    num = mul2(cross, cross);
}

// publish vertical sums, sync, horizontal sums + cc for one output row.
// All 4 divisions of the row folded into one __fdividef.
__device__ __forceinline__ float emit(float* buf, const VS& s, int tid,
                                      F2 NINV, F2 EPS2) {
    {
        ulonglong2 u;
        #pragma unroll
        for (int ch = 0; ch < 5; ch++) {
            u.x = s.v[ch][0].v; u.y = s.v[ch][1].v;
            *(ulonglong2*)&buf[ch * CSTRIDE + 4 + 4 * tid] = u;
        }
    }
    __syncthreads();

    F2 h[5][2];
    #pragma unroll
    for (int ch = 0; ch < 5; ch++) {
        ulonglong2 L = *(ulonglong2*)&buf[ch * CSTRIDE + 4 * tid];
        ulonglong2 R = *(ulonglong2*)&buf[ch * CSTRIDE + 8 + 4 * tid];
        F2 l0, l1, r0, r1;
        l0.v = L.x; l1.v = L.y; r0.v = R.x; r1.v = R.y;
        hsum9p(l0, l1, s.v[ch][0], s.v[ch][1], r0, r1, h[ch][0], h[ch][1]);
    }

    F2 numA, denA, numB, denB;
    ccnd(h[0][0], h[1][0], h[2][0], h[3][0], h[4][0], NINV, EPS2, numA, denA);
    ccnd(h[0][1], h[1][1], h[2][1], h[3][1], h[4][1], NINV, EPS2, numB, denB);
    // packed rational combine: lane-wise nA/dA + nB/dB
    F2 N = fma2(numA, denB, mul2(numB, denA));
    F2 D = mul2(denA, denB);
    float nlo, nhi, dlo, dhi;
    f2up(N, nlo, nhi);
    f2up(D, dlo, dhi);
    float Ns = fmaf(nlo, dhi, nhi * dlo);
    float Ds = dlo * dhi;
    return __fdividef(Ns, Ds);
}

// interior tiles: all rows statically in-bounds -> pointer increments only
__device__ __forceinline__ float loop_interior(const float* __restrict__ Ib,
                                               const float* __restrict__ Tb,
                                               int y0, int tid, float* sm,
                                               F2 H, F2 NEG1, F2 NINV, F2 EPS2,
                                               VS& s) {
    float acc = 0.f;
    const float* iN = Ib + (size_t)(y0 - 4) * IMG_W + 4 * tid;
    const float* tN = Tb + (size_t)(y0 - 4) * IMG_W + 4 * tid;
    ROW cur = ldrowP(iN, tN, H);

    #pragma unroll
    for (int it = 0; it < 8; ++it) {
        iN += IMG_W; tN += IMG_W;
        ROW nxt = ldrowP(iN, tN, H);
        vadd(s, cur);
        cur = nxt;
    }

    // it = 8: add-only, first output; prefetch pair for it=9
    const float* iO = Ib + (size_t)(y0 - 4) * IMG_W + 4 * tid;
    const float* tO = Tb + (size_t)(y0 - 4) * IMG_W + 4 * tid;
    ROW oldp;
    {
        vadd(s, cur);
        oldp = ldrowP(iO, tO, H);
        iN += IMG_W; tN += IMG_W;
        cur = ldrowP(iN, tN, H);
        acc += emit(sm, s, tid, NINV, EPS2);     // parity 0
    }

    // steady state: unconditional prefetch (rows stay in-bounds for interior)
    for (int it = 9; it < HT + 8; ++it) {
        vaddsub(s, cur, oldp, NEG1);
        iO += IMG_W; tO += IMG_W;
        oldp = ldrowP(iO, tO, H);
        iN += IMG_W; tN += IMG_W;
        cur = ldrowP(iN, tN, H);
        acc += emit(sm + (it & 1) * BUFF, s, tid, NINV, EPS2);
    }
    return acc;
}

// edge tiles (bx == 0 or last): bounds-checked index path
__device__ __forceinline__ float loop_edge(const float* __restrict__ Ib,
                                           const float* __restrict__ Tb,
                                           int y0, int iters, int tid, float* sm,
                                           F2 H, F2 NEG1, F2 NINV, F2 EPS2,
                                           VS& s) {
    float acc = 0.f;
    ROW cur = loadrow(Ib, Tb, y0 - 4, tid, H);

    #pragma unroll
    for (int it = 0; it < 8; ++it) {
        ROW nxt = loadrow(Ib, Tb, y0 - 3 + it, tid, H);
        vadd(s, cur);
        cur = nxt;
    }

    ROW oldp;
    {
        vadd(s, cur);
        oldp = loadrow(Ib, Tb, y0 - 4, tid, H);
        cur  = loadrow(Ib, Tb, y0 + 5, tid, H);
        acc += emit(sm, s, tid, NINV, EPS2);
    }

    for (int it = 9; it < iters; ++it) {
        vaddsub(s, cur, oldp, NEG1);
        const int more = (it + 1 < iters);
        oldp = loadrow(Ib, Tb, more ? (y0 - 12 + it) : -1, tid, H);
        cur  = loadrow(Ib, Tb, more ? (y0 - 3 + it)  : -1, tid, H);
        acc += emit(sm + (it & 1) * BUFF, s, tid, NINV, EPS2);
    }
    return acc;
}

__global__ __launch_bounds__(NT, 5)
void cc_kernel(const float* __restrict__ inp, const float* __restrict__ tgt,
               float* __restrict__ out) {
    extern __shared__ float sm[];   // 2 * BUFF floats (double-buffered exchange)

    const int tid = threadIdx.x;
    const int bx  = blockIdx.x;     // ytile
    const int b   = blockIdx.y;     // batch
    const int y0  = bx * HT;
    const int rows_out = min(HT, IMG_H - y0);
    const int iters = rows_out + 8;

    const float* Ib = inp + (size_t)b * IMG_H * IMG_W;
    const float* Tb = tgt + (size_t)b * IMG_H * IMG_W;

    // zero the left/right pads of both buffers (5 channels each)
    for (int i = tid; i < 2 * 5 * 8; i += NT) {
        int bf = i / 40, r = i % 40;
        int ch = r / 8, st = r % 8;
        int idx = (st < 4) ? st : (512 + st);  // 0..3 or 516..519
        sm[bf * BUFF + ch * CSTRIDE + idx] = 0.f;
    }
    __syncthreads();

    const F2 H    = f2pk(0.5f, 0.5f);
    const F2 NEG1 = f2pk(-1.f, -1.f);
    const F2 NINV = f2pk(-1.f / 81.f, -1.f / 81.f);
    const F2 EPS2 = f2pk(1e-5f, 1e-5f);

    VS s;
    #pragma unroll
    for (int c = 0; c < 5; c++) { s.v[c][0] = f2z(); s.v[c][1] = f2z(); }

    float acc;
    if (bx > 0 && bx < YT - 1)
        acc = loop_interior(Ib, Tb, y0, tid, sm, H, NEG1, NINV, EPS2, s);
    else
        acc = loop_edge(Ib, Tb, y0, iters, tid, sm, H, NEG1, NINV, EPS2, s);

    // deterministic block reduction (reuse exchange buffer)
    __syncthreads();
    sm[tid] = acc;
    __syncthreads();
    #pragma unroll
    for (int st = NT / 2; st > 0; st >>= 1) {
        if (tid < st) sm[tid] += sm[tid + st];
        __syncthreads();
    }

    // fused finalize: last CTA reduces all partials in fixed order
    __shared__ unsigned s_last;
    if (tid == 0) {
        g_part[b * YT + bx] = sm[0];
        __threadfence();
        unsigned r = atomicAdd(&g_cnt, 1u);
        s_last = (r == NPART - 1) ? 1u : 0u;
    }
    __syncthreads();
    if (s_last) {
        __threadfence();
        float t = 0.f;
        #pragma unroll
        for (int k = 0; k < (NPART + NT - 1) / NT; k++) {   // fixed order
            int idx = tid + k * NT;
            if (idx < NPART) t += g_part[idx];
        }
        sm[tid] = t;
        __syncthreads();
        #pragma unroll
        for (int st = NT / 2; st > 0; st >>= 1) {
            if (tid < st) sm[tid] += sm[tid + st];
            __syncthreads();
        }
        if (tid == 0) {
            out[0] = -sm[0] * (1.0f / 8388608.0f);
            g_cnt = 0;   // reset for next graph replay
        }
    }
}

extern "C" void kernel_launch(void* const* d_in, const int* in_sizes, int n_in,
                              void* d_out, int out_size) {
    const float* inp = (const float*)d_in[0];
    const float* tgt = (const float*)d_in[1];
    size_t smem = (size_t)(2 * BUFF) * sizeof(float);   // 20.8 KB
    cudaFuncSetAttribute(cc_kernel, cudaFuncAttributeMaxDynamicSharedMemorySize, (int)smem);
    dim3 grid(YT, NB);   // (22, 32) = 704 CTAs, one wave at occ 5
    cc_kernel<<<grid, NT, smem>>>(inp, tgt, (float*)d_out);
}